// round 15
// baseline (speedup 1.0000x reference)
#include <cuda_runtime.h>
#include <cuda_bf16.h>
#include <cstdint>

#define NN 50000
#define NE 800000
#define EPSB 1e-5f

#define TR 128
#define NTILES (NE / TR)      // 6250
#define EDGE_GRID 444         // 3 persistent CTAs/SM
#define SA2 130
#define NT 256
#define GB2_FLOATS (64*SA2 + 8192)
#define GB2_BYTES  (GB2_FLOATS * 4)      // 66048
#define SMEM_FLOATS (64*SA2 + 64*64)
#define SMEM_BYTES  (SMEM_FLOATS * 4)

// ---- edge kernel smem (bytes) ----
#define SAB 72                // bf16 row stride
#define E_A    0
#define E_BHI  18432
#define E_BLO  27648
#define E_SBUF 36864          // 1024 floats stat slots
#define E_SMEM 40960

// ---------------- scratch ----------------
__device__ __align__(16) float g_xw1m[NN * 64];
__device__ __align__(16) float g_xw1n[NN * 64];
__device__ __align__(16) __nv_bfloat16 g_h1[NE * 64];
__device__ __align__(16) float g_hn[NN * 64];
__device__ __align__(16) float g_agg[NN * 64];
__device__ float g_inv[NN];
__device__ int   g_cnt[NN];
__device__ float g_stats[256];
__device__ float g_coef[256];

// ---------------- helpers ----------------
__device__ __forceinline__ void red_add4(float* p, float x, float y, float z, float w) {
    asm volatile("red.global.add.v4.f32 [%0], {%1,%2,%3,%4};"
                 :: "l"(p), "f"(x), "f"(y), "f"(z), "f"(w) : "memory");
}
#define MMA16816(d, a, b) \
    asm volatile("mma.sync.aligned.m16n8k16.row.col.f32.bf16.bf16.f32 " \
        "{%0,%1,%2,%3}, {%4,%5,%6,%7}, {%8,%9}, {%0,%1,%2,%3};" \
        : "+f"((d)[0]), "+f"((d)[1]), "+f"((d)[2]), "+f"((d)[3]) \
        : "r"((a)[0]), "r"((a)[1]), "r"((a)[2]), "r"((a)[3]), "r"((b)[0]), "r"((b)[1]))

__device__ __forceinline__ uint32_t ld32bf(const __nv_bfloat16* p) {
    return *reinterpret_cast<const uint32_t*>(p);
}
__device__ __forceinline__ void convert_B(const float* __restrict__ W,
                                          __nv_bfloat16* Bhi, __nv_bfloat16* Blo, int tid) {
#pragma unroll 4
    for (int it = 0; it < 16; ++it) {
        int idx = tid + it * 256;
        int k = idx >> 6, n = idx & 63;
        float w = __ldg(W + k * 64 + n);
        __nv_bfloat16 hi = __float2bfloat16(w);
        __nv_bfloat16 lo = __float2bfloat16(w - __bfloat162float(hi));
        Bhi[n * SAB + k] = hi;
        Blo[n * SAB + k] = lo;
    }
}

// ---------------- edge1 (R13 config): h1 = bf16(ea @ Wbot + xw1m[send]) ----------------
__global__ void __launch_bounds__(256, 3) k_edge1(
    const float* __restrict__ ea,
    __nv_bfloat16* __restrict__ h1out,
    const int*   __restrict__ ei,
    const float* __restrict__ W)
{
    extern __shared__ char smem[];
    __nv_bfloat16* A_s = (__nv_bfloat16*)(smem + E_A);
    __nv_bfloat16* Bhi = (__nv_bfloat16*)(smem + E_BHI);
    __nv_bfloat16* Blo = (__nv_bfloat16*)(smem + E_BLO);
    float* sbuf = (float*)(smem + E_SBUF);

    const int tid = threadIdx.x;
    convert_B(W, Bhi, Blo, tid);

    const int w = tid >> 5, l = tid & 31;
    const int g = l >> 2, tg = l & 3;
    const int mrow = (w >> 1) * 32, ncol = (w & 1) * 32;
    const int cg = tid & 7;

    float s8[8], q8[8];
#pragma unroll
    for (int j = 0; j < 8; ++j) { s8[j] = 0.f; q8[j] = 0.f; }

    const float4* src4 = reinterpret_cast<const float4*>(ea);

    for (int t = blockIdx.x; t < NTILES; t += EDGE_GRID) {
        const int base = t * TR;
        __syncthreads();
#pragma unroll 4
        for (int it = 0; it < 8; ++it) {
            int chunk = tid + it * 256;
            int row = chunk >> 4, c4 = chunk & 15;
            float4 v = __ldg(src4 + (long long)(base + row) * 16 + c4);
            __nv_bfloat162 b01 = __float22bfloat162_rn(make_float2(v.x, v.y));
            __nv_bfloat162 b23 = __float22bfloat162_rn(make_float2(v.z, v.w));
            *reinterpret_cast<uint2*>(A_s + row * SAB + c4 * 4) =
                make_uint2(*reinterpret_cast<uint32_t*>(&b01),
                           *reinterpret_cast<uint32_t*>(&b23));
        }
        __syncthreads();

        float d[2][4][4];
#pragma unroll
        for (int mt = 0; mt < 2; ++mt)
#pragma unroll
            for (int nt = 0; nt < 4; ++nt)
#pragma unroll
                for (int j = 0; j < 4; ++j) d[mt][nt][j] = 0.f;

#pragma unroll
        for (int kit = 0; kit < 4; ++kit) {
            const int kb = kit * 16 + 2 * tg;
            uint32_t a[2][4], bhi[4][2], blo[4][2];
#pragma unroll
            for (int mt = 0; mt < 2; ++mt) {
                const int r = mrow + mt * 16 + g;
                a[mt][0] = ld32bf(A_s + r * SAB + kb);
                a[mt][1] = ld32bf(A_s + (r + 8) * SAB + kb);
                a[mt][2] = ld32bf(A_s + r * SAB + kb + 8);
                a[mt][3] = ld32bf(A_s + (r + 8) * SAB + kb + 8);
            }
#pragma unroll
            for (int nt = 0; nt < 4; ++nt) {
                const int n = ncol + nt * 8 + g;
                bhi[nt][0] = ld32bf(Bhi + n * SAB + kb);
                bhi[nt][1] = ld32bf(Bhi + n * SAB + kb + 8);
                blo[nt][0] = ld32bf(Blo + n * SAB + kb);
                blo[nt][1] = ld32bf(Blo + n * SAB + kb + 8);
            }
#pragma unroll
            for (int mt = 0; mt < 2; ++mt)
#pragma unroll
                for (int nt = 0; nt < 4; ++nt) {
                    MMA16816(d[mt][nt], a[mt], bhi[nt]);
                    MMA16816(d[mt][nt], a[mt], blo[nt]);
                }
        }
        __syncthreads();

        // stage d (bf16) back into A_s
#pragma unroll
        for (int mt = 0; mt < 2; ++mt)
#pragma unroll
            for (int h = 0; h < 2; ++h) {
                const int rl = mrow + mt * 16 + g + h * 8;
#pragma unroll
                for (int nt = 0; nt < 4; ++nt) {
                    const int c = ncol + nt * 8 + 2 * tg;
                    __nv_bfloat162 hv = __float22bfloat162_rn(
                        make_float2(d[mt][nt][h * 2 + 0], d[mt][nt][h * 2 + 1]));
                    *reinterpret_cast<uint32_t*>(A_s + rl * SAB + c) =
                        *reinterpret_cast<uint32_t*>(&hv);
                }
            }
        __syncthreads();

        // chunk-linear epilogue
#pragma unroll
        for (int it = 0; it < 4; ++it) {
            const int chunk = tid + it * 256;
            const int row = chunk >> 3;
            const long long rr = base + row;
            const int snd = __ldg(ei + rr);
            if (cg == 0) atomicAdd(&g_cnt[__ldg(ei + NE + rr)], 1);
            uint4 raw = *reinterpret_cast<const uint4*>(A_s + row * SAB + cg * 8);
            const uint32_t* rw = reinterpret_cast<const uint32_t*>(&raw);
            float4 x0 = __ldg(reinterpret_cast<const float4*>(g_xw1m + (long long)snd * 64 + cg * 8));
            float4 x1 = __ldg(reinterpret_cast<const float4*>(g_xw1m + (long long)snd * 64 + cg * 8 + 4));
            const float xv[8] = {x0.x, x0.y, x0.z, x0.w, x1.x, x1.y, x1.z, x1.w};
            uint32_t outp[4];
#pragma unroll
            for (int p = 0; p < 4; ++p) {
                float2 hv = __bfloat1622float2(*reinterpret_cast<const __nv_bfloat162*>(&rw[p]));
                float v0 = hv.x + xv[p * 2 + 0];
                float v1 = hv.y + xv[p * 2 + 1];
                s8[p * 2 + 0] += v0; q8[p * 2 + 0] += v0 * v0;
                s8[p * 2 + 1] += v1; q8[p * 2 + 1] += v1 * v1;
                __nv_bfloat162 o2 = __float22bfloat162_rn(make_float2(v0, v1));
                outp[p] = *reinterpret_cast<uint32_t*>(&o2);
            }
            *reinterpret_cast<uint4*>(h1out + rr * 64 + cg * 8) =
                make_uint4(outp[0], outp[1], outp[2], outp[3]);
        }
    }

#pragma unroll
    for (int off = 8; off < 32; off <<= 1) {
#pragma unroll
        for (int j = 0; j < 8; ++j) {
            s8[j] += __shfl_xor_sync(0xFFFFFFFFu, s8[j], off);
            q8[j] += __shfl_xor_sync(0xFFFFFFFFu, q8[j], off);
        }
    }
    __syncthreads();
    if (l < 8) {
#pragma unroll
        for (int j = 0; j < 8; ++j) {
            sbuf[w * 64 + l * 8 + j]       = s8[j];
            sbuf[512 + w * 64 + l * 8 + j] = q8[j];
        }
    }
    __syncthreads();
    if (tid < 128) {
        const int stat = tid >> 6, c = tid & 63;
        float a = 0.f;
#pragma unroll
        for (int ww = 0; ww < 8; ++ww) a += sbuf[stat * 512 + ww * 64 + c];
        atomicAdd(&g_stats[stat * 64 + c], a);
    }
}

// ---------------- edge2: relu(BN(h1)) @ W2 + b2 -> staged chunk-linear red.add.v4 ----------------
__global__ void __launch_bounds__(256, 3) k_edge2(
    const __nv_bfloat16* __restrict__ h1in,
    const int*   __restrict__ ei,
    const float* __restrict__ W2,
    const float* __restrict__ b2)
{
    extern __shared__ char smem[];
    __nv_bfloat16* A_s = (__nv_bfloat16*)(smem + E_A);
    __nv_bfloat16* Bhi = (__nv_bfloat16*)(smem + E_BHI);
    __nv_bfloat16* Blo = (__nv_bfloat16*)(smem + E_BLO);

    const int tid = threadIdx.x;
    convert_B(W2, Bhi, Blo, tid);

    const int w = tid >> 5, l = tid & 31;
    const int g = l >> 2, tg = l & 3;
    const int mrow = (w >> 1) * 32, ncol = (w & 1) * 32;
    const int cg = tid & 7;

    // per-thread bias for its fixed column chunk
    const float4 bb0 = *reinterpret_cast<const float4*>(b2 + cg * 8);
    const float4 bb1 = *reinterpret_cast<const float4*>(b2 + cg * 8 + 4);

    const uint4* src = reinterpret_cast<const uint4*>(h1in);

    for (int t = blockIdx.x; t < NTILES; t += EDGE_GRID) {
        const int base = t * TR;
        __syncthreads();
#pragma unroll
        for (int it = 0; it < 4; ++it) {
            int chunk = tid + it * 256;
            int row = chunk >> 3, c8 = chunk & 7;
            uint4 raw = __ldg(src + (long long)(base + row) * 8 + c8);
            const uint32_t* rw = reinterpret_cast<const uint32_t*>(&raw);
            uint32_t outp[4];
#pragma unroll
            for (int p = 0; p < 4; ++p) {
                float2 hv = __bfloat1622float2(*reinterpret_cast<const __nv_bfloat162*>(&rw[p]));
                int c = c8 * 8 + p * 2;
                float2 cs = *reinterpret_cast<const float2*>(g_coef + c);
                float2 ch = *reinterpret_cast<const float2*>(g_coef + 64 + c);
                float vx = fmaxf(fmaf(hv.x, cs.x, ch.x), 0.f);
                float vy = fmaxf(fmaf(hv.y, cs.y, ch.y), 0.f);
                __nv_bfloat162 o2 = __float22bfloat162_rn(make_float2(vx, vy));
                outp[p] = *reinterpret_cast<uint32_t*>(&o2);
            }
            *reinterpret_cast<uint4*>(A_s + row * SAB + c8 * 8) =
                make_uint4(outp[0], outp[1], outp[2], outp[3]);
        }
        __syncthreads();

        float d[2][4][4];
#pragma unroll
        for (int mt = 0; mt < 2; ++mt)
#pragma unroll
            for (int nt = 0; nt < 4; ++nt)
#pragma unroll
                for (int j = 0; j < 4; ++j) d[mt][nt][j] = 0.f;

#pragma unroll
        for (int kit = 0; kit < 4; ++kit) {
            const int kb = kit * 16 + 2 * tg;
            uint32_t a[2][4], bhi[4][2], blo[4][2];
#pragma unroll
            for (int mt = 0; mt < 2; ++mt) {
                const int r = mrow + mt * 16 + g;
                a[mt][0] = ld32bf(A_s + r * SAB + kb);
                a[mt][1] = ld32bf(A_s + (r + 8) * SAB + kb);
                a[mt][2] = ld32bf(A_s + r * SAB + kb + 8);
                a[mt][3] = ld32bf(A_s + (r + 8) * SAB + kb + 8);
            }
#pragma unroll
            for (int nt = 0; nt < 4; ++nt) {
                const int n = ncol + nt * 8 + g;
                bhi[nt][0] = ld32bf(Bhi + n * SAB + kb);
                bhi[nt][1] = ld32bf(Bhi + n * SAB + kb + 8);
                blo[nt][0] = ld32bf(Blo + n * SAB + kb);
                blo[nt][1] = ld32bf(Blo + n * SAB + kb + 8);
            }
#pragma unroll
            for (int mt = 0; mt < 2; ++mt)
#pragma unroll
                for (int nt = 0; nt < 4; ++nt) {
                    MMA16816(d[mt][nt], a[mt], bhi[nt]);
                    MMA16816(d[mt][nt], a[mt], blo[nt]);
                }
        }
        __syncthreads();

        // stage m (bf16) back into A_s
#pragma unroll
        for (int mt = 0; mt < 2; ++mt)
#pragma unroll
            for (int h = 0; h < 2; ++h) {
                const int rl = mrow + mt * 16 + g + h * 8;
#pragma unroll
                for (int nt = 0; nt < 4; ++nt) {
                    const int c = ncol + nt * 8 + 2 * tg;
                    __nv_bfloat162 hv = __float22bfloat162_rn(
                        make_float2(d[mt][nt][h * 2 + 0], d[mt][nt][h * 2 + 1]));
                    *reinterpret_cast<uint32_t*>(A_s + rl * SAB + c) =
                        *reinterpret_cast<uint32_t*>(&hv);
                }
            }
        __syncthreads();

        // chunk-linear scatter: 2x red.add.v4 per 16B chunk
#pragma unroll
        for (int it = 0; it < 4; ++it) {
            const int chunk = tid + it * 256;
            const int row = chunk >> 3;
            const long long rr = base + row;
            const int rec = __ldg(ei + NE + rr);
            uint4 raw = *reinterpret_cast<const uint4*>(A_s + row * SAB + cg * 8);
            const uint32_t* rw = reinterpret_cast<const uint32_t*>(&raw);
            float2 m0 = __bfloat1622float2(*reinterpret_cast<const __nv_bfloat162*>(&rw[0]));
            float2 m1 = __bfloat1622float2(*reinterpret_cast<const __nv_bfloat162*>(&rw[1]));
            float2 m2 = __bfloat1622float2(*reinterpret_cast<const __nv_bfloat162*>(&rw[2]));
            float2 m3 = __bfloat1622float2(*reinterpret_cast<const __nv_bfloat162*>(&rw[3]));
            float* dst = g_agg + (long long)rec * 64 + cg * 8;
            red_add4(dst,     m0.x + bb0.x, m0.y + bb0.y, m1.x + bb0.z, m1.y + bb0.w);
            red_add4(dst + 4, m2.x + bb1.x, m2.y + bb1.y, m3.x + bb1.z, m3.y + bb1.w);
        }
    }
}

// ---------------- fp32x2 node-side kernels ----------------
__device__ __forceinline__ void load_W(const float* __restrict__ W, float* W_s, int tid) {
    const float4* wg = reinterpret_cast<const float4*>(W);
    float4* ws = reinterpret_cast<float4*>(W_s);
#pragma unroll
    for (int j = 0; j < 4; ++j) ws[tid + j * NT] = wg[tid + j * NT];
}
__device__ __forceinline__ float2 unpack2(unsigned long long v) {
    float2 r;
    asm("mov.b64 {%0,%1}, %2;" : "=f"(r.x), "=f"(r.y) : "l"(v));
    return r;
}
__device__ __forceinline__ void mm64x2(const float* __restrict__ A_s,
                                       const float* __restrict__ W_s,
                                       int rg, int c4, unsigned long long acc[4][4]) {
#pragma unroll 8
    for (int k = 0; k < 64; ++k) {
        const float4 b = *reinterpret_cast<const float4*>(W_s + k * 64 + c4 * 4);
        unsigned long long bd0, bd1, bd2, bd3;
        asm("mov.b64 %0,{%1,%1};" : "=l"(bd0) : "f"(b.x));
        asm("mov.b64 %0,{%1,%1};" : "=l"(bd1) : "f"(b.y));
        asm("mov.b64 %0,{%1,%1};" : "=l"(bd2) : "f"(b.z));
        asm("mov.b64 %0,{%1,%1};" : "=l"(bd3) : "f"(b.w));
        const unsigned long long* ap =
            reinterpret_cast<const unsigned long long*>(A_s + k * SA2 + rg * 8);
#pragma unroll
        for (int i = 0; i < 4; ++i) {
            unsigned long long a = ap[i];
            asm("fma.rn.f32x2 %0, %1, %2, %0;" : "+l"(acc[i][0]) : "l"(a), "l"(bd0));
            asm("fma.rn.f32x2 %0, %1, %2, %0;" : "+l"(acc[i][1]) : "l"(a), "l"(bd1));
            asm("fma.rn.f32x2 %0, %1, %2, %0;" : "+l"(acc[i][2]) : "l"(a), "l"(bd2));
            asm("fma.rn.f32x2 %0, %1, %2, %0;" : "+l"(acc[i][3]) : "l"(a), "l"(bd3));
        }
    }
}
#define ZERO_ACC2(acc) do { \
    _Pragma("unroll") for (int _i = 0; _i < 4; ++_i) { \
        acc[_i][0]=0ull; acc[_i][1]=0ull; acc[_i][2]=0ull; acc[_i][3]=0ull; } } while (0)

__device__ __forceinline__ void stat_reduce(float* buf, int tid, int rg, int c4,
                                            const float s[4], const float q[4], int off) {
    __syncthreads();
#pragma unroll
    for (int j = 0; j < 4; ++j) {
        buf[rg * 64 + c4 * 4 + j]        = s[j];
        buf[1024 + rg * 64 + c4 * 4 + j] = q[j];
    }
    __syncthreads();
    if (tid < 128) {
        int c = tid & 63, which = tid >> 6;
        float a = 0.f;
#pragma unroll
        for (int gg = 0; gg < 16; ++gg) a += buf[which * 1024 + gg * 64 + c];
        atomicAdd(&g_stats[off + which * 64 + c], a);
    }
}

__global__ void k_zero() {
    int i = blockIdx.x * blockDim.x + threadIdx.x;
    if (i < NN * 64) g_agg[i] = 0.f;
    if (i < NN)      g_cnt[i] = 0;
    if (i < 256)     g_stats[i] = 0.f;
}
__global__ void k_inv() {
    int i = blockIdx.x * blockDim.x + threadIdx.x;
    if (i < NN) g_inv[i] = 1.0f / fmaxf((float)g_cnt[i], 1.0f);
}
__global__ void k_coef(int off, float invR,
                       const float* __restrict__ gamma, const float* __restrict__ beta) {
    int c = threadIdx.x;
    float mean = g_stats[off + c] * invR;
    float ms   = g_stats[off + 64 + c] * invR;
    float var  = ms - mean * mean;
    float sc   = gamma[c] * rsqrtf(var + EPSB);
    g_coef[off + c]      = sc;
    g_coef[off + 64 + c] = beta[c] - mean * sc;
}

// fused: xw1m = x@W1m + b1m ; xw1n = x@W1n + b1n  (x tile loaded once)
__global__ void k_gemm_bias2(const float* __restrict__ A,
                             const float* __restrict__ W1, const float* __restrict__ b1v,
                             const float* __restrict__ W2v, const float* __restrict__ b2v,
                             float* __restrict__ out1, float* __restrict__ out2) {
    extern __shared__ float smemf[];
    float* A_s = smemf;
    float* W_s = smemf + 64 * SA2;
    const int tid = threadIdx.x;
    const int base = blockIdx.x * TR;
    load_W(W1, W_s, tid);
    load_W(W2v, W_s + 4096, tid);
#pragma unroll
    for (int j = 0; j < 32; ++j) {
        int idx = tid + j * NT;
        int k = idx & 63, row = idx >> 6;
        int r = base + row; if (r > NN - 1) r = NN - 1;
        A_s[k * SA2 + row] = A[r * 64 + k];
    }
    __syncthreads();
    const int c4 = tid & 15, rg = tid >> 4;
    unsigned long long acc[4][4];
#pragma unroll
    for (int which = 0; which < 2; ++which) {
        ZERO_ACC2(acc);
        mm64x2(A_s, W_s + which * 4096, rg, c4, acc);
        const float* bias = (which == 0) ? b1v : b2v;
        float* out = (which == 0) ? out1 : out2;
        const float4 bb = *reinterpret_cast<const float4*>(bias + c4 * 4);
#pragma unroll
        for (int i = 0; i < 4; ++i) {
            float2 p0 = unpack2(acc[i][0]), p1 = unpack2(acc[i][1]);
            float2 p2 = unpack2(acc[i][2]), p3 = unpack2(acc[i][3]);
            int r0 = base + rg * 8 + 2 * i;
            if (r0 < NN)
                *reinterpret_cast<float4*>(out + r0 * 64 + c4 * 4) =
                    make_float4(p0.x + bb.x, p1.x + bb.y, p2.x + bb.z, p3.x + bb.w);
            if (r0 + 1 < NN)
                *reinterpret_cast<float4*>(out + (r0 + 1) * 64 + c4 * 4) =
                    make_float4(p0.y + bb.x, p1.y + bb.y, p2.y + bb.z, p3.y + bb.w);
        }
    }
}

__global__ void k_node1(const float* __restrict__ Wbot) {
    extern __shared__ float smemf[];
    float* A_s = smemf;
    float* W_s = smemf + 64 * SA2;
    const int tid = threadIdx.x;
    const int base = blockIdx.x * TR;
    load_W(Wbot, W_s, tid);
#pragma unroll
    for (int j = 0; j < 32; ++j) {
        int idx = tid + j * NT;
        int k = idx & 63, row = idx >> 6;
        int r = base + row; if (r > NN - 1) r = NN - 1;
        A_s[k * SA2 + row] = g_agg[r * 64 + k] * g_inv[r];
    }
    __syncthreads();
    const int c4 = tid & 15, rg = tid >> 4;
    unsigned long long acc[4][4];
    ZERO_ACC2(acc);
    mm64x2(A_s, W_s, rg, c4, acc);
    float s[4] = {0.f,0.f,0.f,0.f}, q[4] = {0.f,0.f,0.f,0.f};
#pragma unroll
    for (int i = 0; i < 4; ++i) {
        float2 p0 = unpack2(acc[i][0]), p1 = unpack2(acc[i][1]);
        float2 p2 = unpack2(acc[i][2]), p3 = unpack2(acc[i][3]);
        int r0 = base + rg * 8 + 2 * i;
        if (r0 < NN) {
            float4 xw = *reinterpret_cast<const float4*>(g_xw1n + r0 * 64 + c4 * 4);
            float4 v = make_float4(p0.x + xw.x, p1.x + xw.y, p2.x + xw.z, p3.x + xw.w);
            *reinterpret_cast<float4*>(g_hn + r0 * 64 + c4 * 4) = v;
            s[0] += v.x; q[0] += v.x * v.x; s[1] += v.y; q[1] += v.y * v.y;
            s[2] += v.z; q[2] += v.z * v.z; s[3] += v.w; q[3] += v.w * v.w;
        }
        if (r0 + 1 < NN) {
            float4 xw = *reinterpret_cast<const float4*>(g_xw1n + (r0 + 1) * 64 + c4 * 4);
            float4 v = make_float4(p0.y + xw.x, p1.y + xw.y, p2.y + xw.z, p3.y + xw.w);
            *reinterpret_cast<float4*>(g_hn + (r0 + 1) * 64 + c4 * 4) = v;
            s[0] += v.x; q[0] += v.x * v.x; s[1] += v.y; q[1] += v.y * v.y;
            s[2] += v.z; q[2] += v.z * v.z; s[3] += v.w; q[3] += v.w * v.w;
        }
    }
    stat_reduce(A_s, tid, rg, c4, s, q, 128);
}
__global__ void k_node2(const float* __restrict__ W2,
                        const float* __restrict__ b2,
                        float* __restrict__ out) {
    extern __shared__ float smemf[];
    float* A_s = smemf;
    float* W_s = smemf + 64 * SA2;
    const int tid = threadIdx.x;
    const int base = blockIdx.x * TR;
    load_W(W2, W_s, tid);
    const float cs = g_coef[128 + (tid & 63)];
    const float ch = g_coef[192 + (tid & 63)];
#pragma unroll
    for (int j = 0; j < 32; ++j) {
        int idx = tid + j * NT;
        int k = idx & 63, row = idx >> 6;
        int r = base + row; if (r > NN - 1) r = NN - 1;
        float v = fmaf(g_hn[r * 64 + k], cs, ch);
        A_s[k * SA2 + row] = fmaxf(v, 0.f);
    }
    __syncthreads();
    const int c4 = tid & 15, rg = tid >> 4;
    unsigned long long acc[4][4];
    ZERO_ACC2(acc);
    mm64x2(A_s, W_s, rg, c4, acc);
    const float4 bb = *reinterpret_cast<const float4*>(b2 + c4 * 4);
#pragma unroll
    for (int i = 0; i < 4; ++i) {
        float2 p0 = unpack2(acc[i][0]), p1 = unpack2(acc[i][1]);
        float2 p2 = unpack2(acc[i][2]), p3 = unpack2(acc[i][3]);
        int r0 = base + rg * 8 + 2 * i;
        if (r0 < NN)
            *reinterpret_cast<float4*>(out + r0 * 64 + c4 * 4) =
                make_float4(p0.x + bb.x, p1.x + bb.y, p2.x + bb.z, p3.x + bb.w);
        if (r0 + 1 < NN)
            *reinterpret_cast<float4*>(out + (r0 + 1) * 64 + c4 * 4) =
                make_float4(p0.y + bb.x, p1.y + bb.y, p2.y + bb.z, p3.y + bb.w);
    }
}

// ---------------- launch ----------------
extern "C" void kernel_launch(void* const* d_in, const int* in_sizes, int n_in,
                              void* d_out, int out_size) {
    const float* x   = (const float*)d_in[0];
    const int*   ei  = (const int*)d_in[1];
    const float* ea  = (const float*)d_in[2];
    const float* w1m = (const float*)d_in[5];
    const float* b1m = (const float*)d_in[6];
    const float* gm  = (const float*)d_in[7];
    const float* bm  = (const float*)d_in[8];
    const float* w2m = (const float*)d_in[9];
    const float* b2m = (const float*)d_in[10];
    const float* w1n = (const float*)d_in[11];
    const float* b1n = (const float*)d_in[12];
    const float* gn  = (const float*)d_in[13];
    const float* bn  = (const float*)d_in[14];
    const float* w2n = (const float*)d_in[15];
    const float* b2n = (const float*)d_in[16];
    float* out = (float*)d_out;

    cudaFuncSetAttribute(k_gemm_bias2, cudaFuncAttributeMaxDynamicSharedMemorySize, GB2_BYTES);
    cudaFuncSetAttribute(k_node1,      cudaFuncAttributeMaxDynamicSharedMemorySize, SMEM_BYTES);
    cudaFuncSetAttribute(k_node2,      cudaFuncAttributeMaxDynamicSharedMemorySize, SMEM_BYTES);
    cudaFuncSetAttribute(k_edge1,      cudaFuncAttributeMaxDynamicSharedMemorySize, E_SMEM);
    cudaFuncSetAttribute(k_edge2,      cudaFuncAttributeMaxDynamicSharedMemorySize, E_SMEM);

    float *p_xw1m, *p_xw1n;
    __nv_bfloat16* p_h1;
    cudaGetSymbolAddress((void**)&p_xw1m, g_xw1m);
    cudaGetSymbolAddress((void**)&p_xw1n, g_xw1n);
    cudaGetSymbolAddress((void**)&p_h1,   g_h1);

    const int nodeBlocks = (NN + TR - 1) / TR;

    k_zero<<<(NN * 64 + NT - 1) / NT, NT>>>();
    k_gemm_bias2<<<nodeBlocks, NT, GB2_BYTES>>>(x, w1m, b1m, w1n, b1n, p_xw1m, p_xw1n);
    k_edge1<<<EDGE_GRID, 256, E_SMEM>>>(ea, p_h1, ei, w1m + 64 * 64);
    k_inv<<<(NN + NT - 1) / NT, NT>>>();
    k_coef<<<1, 64>>>(0, 1.0f / (float)NE, gm, bm);
    k_edge2<<<EDGE_GRID, 256, E_SMEM>>>(p_h1, ei, w2m, b2m);
    k_node1<<<nodeBlocks, NT, SMEM_BYTES>>>(w1n + 64 * 64);
    k_coef<<<1, 64>>>(128, 1.0f / (float)NN, gn, bn);
    k_node2<<<nodeBlocks, NT, SMEM_BYTES>>>(w2n, b2n, out);
}

// round 16
// speedup vs baseline: 1.4836x; 1.4836x over previous
#include <cuda_runtime.h>
#include <cuda_bf16.h>
#include <cstdint>

#define NN 50000
#define NE 800000
#define EPSB 1e-5f

#define TR 128
#define NTILES (NE / TR)      // 6250
#define E1_GRID 592           // 4 persistent CTAs/SM
#define E2_GRID 444           // 3 persistent CTAs/SM
#define SA2 130
#define NT 256
#define GB2_FLOATS (64*SA2 + 8192)
#define GB2_BYTES  (GB2_FLOATS * 4)      // 66048
#define SMEM_FLOATS (64*SA2 + 64*64)
#define SMEM_BYTES  (SMEM_FLOATS * 4)

// ---- edge kernel smem (bytes) ----
#define SAB 72                // bf16 row stride
#define E_A    0
#define E_BHI  18432
#define E_BLO  27648
#define E_SBUF 36864          // 1024 floats stat slots
#define E_SMEM 40960

// ---------------- scratch ----------------
__device__ __align__(16) float g_xw1m[NN * 64];
__device__ __align__(16) float g_xw1n[NN * 64];
__device__ __align__(16) __nv_bfloat16 g_h1[NE * 64];
__device__ __align__(16) float g_hn[NN * 64];
__device__ __align__(16) float g_agg[NN * 64];
__device__ float g_inv[NN];
__device__ int   g_cnt[NN];
__device__ float g_stats[256];
__device__ float g_coef[256];

// ---------------- helpers ----------------
__device__ __forceinline__ void red_add2(float* p, float x, float y) {
    asm volatile("red.global.add.v2.f32 [%0], {%1,%2};" :: "l"(p), "f"(x), "f"(y) : "memory");
}
#define MMA16816(d, a, b) \
    asm volatile("mma.sync.aligned.m16n8k16.row.col.f32.bf16.bf16.f32 " \
        "{%0,%1,%2,%3}, {%4,%5,%6,%7}, {%8,%9}, {%0,%1,%2,%3};" \
        : "+f"((d)[0]), "+f"((d)[1]), "+f"((d)[2]), "+f"((d)[3]) \
        : "r"((a)[0]), "r"((a)[1]), "r"((a)[2]), "r"((a)[3]), "r"((b)[0]), "r"((b)[1]))

__device__ __forceinline__ uint32_t ld32bf(const __nv_bfloat16* p) {
    return *reinterpret_cast<const uint32_t*>(p);
}
__device__ __forceinline__ void convert_B(const float* __restrict__ W,
                                          __nv_bfloat16* Bhi, __nv_bfloat16* Blo, int tid) {
#pragma unroll 4
    for (int it = 0; it < 16; ++it) {
        int idx = tid + it * 256;
        int k = idx >> 6, n = idx & 63;
        float w = __ldg(W + k * 64 + n);
        __nv_bfloat16 hi = __float2bfloat16(w);
        __nv_bfloat16 lo = __float2bfloat16(w - __bfloat162float(hi));
        Bhi[n * SAB + k] = hi;
        Blo[n * SAB + k] = lo;
    }
}

// ---------------- edge1: h1 = bf16(ea @ Wbot + xw1m[send]), fused stats + counts ----------------
__global__ void __launch_bounds__(256, 4) k_edge1(
    const float* __restrict__ ea,
    __nv_bfloat16* __restrict__ h1out,
    const int*   __restrict__ ei,
    const float* __restrict__ W)
{
    extern __shared__ char smem[];
    __nv_bfloat16* A_s = (__nv_bfloat16*)(smem + E_A);
    __nv_bfloat16* Bhi = (__nv_bfloat16*)(smem + E_BHI);
    __nv_bfloat16* Blo = (__nv_bfloat16*)(smem + E_BLO);
    float* sbuf = (float*)(smem + E_SBUF);

    const int tid = threadIdx.x;
    convert_B(W, Bhi, Blo, tid);
#pragma unroll
    for (int i = tid; i < 1024; i += 256) sbuf[i] = 0.f;

    const int w = tid >> 5, l = tid & 31;
    const int g = l >> 2, tg = l & 3;
    const int mrow = (w >> 1) * 32, ncol = (w & 1) * 32;
    const int cg = tid & 7;

    const float4* src4 = reinterpret_cast<const float4*>(ea);

    for (int t = blockIdx.x; t < NTILES; t += E1_GRID) {
        const int base = t * TR;
        __syncthreads();
#pragma unroll 4
        for (int it = 0; it < 8; ++it) {
            int chunk = tid + it * 256;
            int row = chunk >> 4, c4 = chunk & 15;
            float4 v = __ldg(src4 + (long long)(base + row) * 16 + c4);
            __nv_bfloat162 b01 = __float22bfloat162_rn(make_float2(v.x, v.y));
            __nv_bfloat162 b23 = __float22bfloat162_rn(make_float2(v.z, v.w));
            *reinterpret_cast<uint2*>(A_s + row * SAB + c4 * 4) =
                make_uint2(*reinterpret_cast<uint32_t*>(&b01),
                           *reinterpret_cast<uint32_t*>(&b23));
        }
        __syncthreads();

        float d[2][4][4];
#pragma unroll
        for (int mt = 0; mt < 2; ++mt)
#pragma unroll
            for (int nt = 0; nt < 4; ++nt)
#pragma unroll
                for (int j = 0; j < 4; ++j) d[mt][nt][j] = 0.f;

#pragma unroll
        for (int kit = 0; kit < 4; ++kit) {
            const int kb = kit * 16 + 2 * tg;
            uint32_t a[2][4], bhi[4][2], blo[4][2];
#pragma unroll
            for (int mt = 0; mt < 2; ++mt) {
                const int r = mrow + mt * 16 + g;
                a[mt][0] = ld32bf(A_s + r * SAB + kb);
                a[mt][1] = ld32bf(A_s + (r + 8) * SAB + kb);
                a[mt][2] = ld32bf(A_s + r * SAB + kb + 8);
                a[mt][3] = ld32bf(A_s + (r + 8) * SAB + kb + 8);
            }
#pragma unroll
            for (int nt = 0; nt < 4; ++nt) {
                const int n = ncol + nt * 8 + g;
                bhi[nt][0] = ld32bf(Bhi + n * SAB + kb);
                bhi[nt][1] = ld32bf(Bhi + n * SAB + kb + 8);
                blo[nt][0] = ld32bf(Blo + n * SAB + kb);
                blo[nt][1] = ld32bf(Blo + n * SAB + kb + 8);
            }
#pragma unroll
            for (int mt = 0; mt < 2; ++mt)
#pragma unroll
                for (int nt = 0; nt < 4; ++nt) {
                    MMA16816(d[mt][nt], a[mt], bhi[nt]);
                    MMA16816(d[mt][nt], a[mt], blo[nt]);
                }
        }
        __syncthreads();

        // stage d (bf16) back into A_s
#pragma unroll
        for (int mt = 0; mt < 2; ++mt)
#pragma unroll
            for (int h = 0; h < 2; ++h) {
                const int rl = mrow + mt * 16 + g + h * 8;
#pragma unroll
                for (int nt = 0; nt < 4; ++nt) {
                    const int c = ncol + nt * 8 + 2 * tg;
                    __nv_bfloat162 hv = __float22bfloat162_rn(
                        make_float2(d[mt][nt][h * 2 + 0], d[mt][nt][h * 2 + 1]));
                    *reinterpret_cast<uint32_t*>(A_s + rl * SAB + c) =
                        *reinterpret_cast<uint32_t*>(&hv);
                }
            }
        __syncthreads();

        // chunk-linear epilogue; per-tile local stats
        float s8[8], q8[8];
#pragma unroll
        for (int j = 0; j < 8; ++j) { s8[j] = 0.f; q8[j] = 0.f; }
#pragma unroll
        for (int it = 0; it < 4; ++it) {
            const int chunk = tid + it * 256;
            const int row = chunk >> 3;
            const long long rr = base + row;
            const int snd = __ldg(ei + rr);
            if (cg == 0) atomicAdd(&g_cnt[__ldg(ei + NE + rr)], 1);
            uint4 raw = *reinterpret_cast<const uint4*>(A_s + row * SAB + cg * 8);
            const uint32_t* rw = reinterpret_cast<const uint32_t*>(&raw);
            float4 x0 = __ldg(reinterpret_cast<const float4*>(g_xw1m + (long long)snd * 64 + cg * 8));
            float4 x1 = __ldg(reinterpret_cast<const float4*>(g_xw1m + (long long)snd * 64 + cg * 8 + 4));
            const float xv[8] = {x0.x, x0.y, x0.z, x0.w, x1.x, x1.y, x1.z, x1.w};
            uint32_t outp[4];
#pragma unroll
            for (int p = 0; p < 4; ++p) {
                float2 hv = __bfloat1622float2(*reinterpret_cast<const __nv_bfloat162*>(&rw[p]));
                float v0 = hv.x + xv[p * 2 + 0];
                float v1 = hv.y + xv[p * 2 + 1];
                s8[p * 2 + 0] += v0; q8[p * 2 + 0] += v0 * v0;
                s8[p * 2 + 1] += v1; q8[p * 2 + 1] += v1 * v1;
                __nv_bfloat162 o2 = __float22bfloat162_rn(make_float2(v0, v1));
                outp[p] = *reinterpret_cast<uint32_t*>(&o2);
            }
            *reinterpret_cast<uint4*>(h1out + rr * 64 + cg * 8) =
                make_uint4(outp[0], outp[1], outp[2], outp[3]);
        }
        // warp-reduce + accumulate into per-warp smem slots
#pragma unroll
        for (int off = 8; off < 32; off <<= 1) {
#pragma unroll
            for (int j = 0; j < 8; ++j) {
                s8[j] += __shfl_xor_sync(0xFFFFFFFFu, s8[j], off);
                q8[j] += __shfl_xor_sync(0xFFFFFFFFu, q8[j], off);
            }
        }
        if (l < 8) {
#pragma unroll
            for (int j = 0; j < 8; ++j) {
                sbuf[w * 64 + l * 8 + j]       += s8[j];
                sbuf[512 + w * 64 + l * 8 + j] += q8[j];
            }
        }
    }

    __syncthreads();
    if (tid < 128) {
        const int stat = tid >> 6, c = tid & 63;
        float a = 0.f;
#pragma unroll
        for (int ww = 0; ww < 8; ++ww) a += sbuf[stat * 512 + ww * 64 + c];
        atomicAdd(&g_stats[stat * 64 + c], a);
    }
}

// ---------------- edge2: relu(BN(h1)) @ W2 + b2 -> red.add g_agg[rec] (R14 form) ----------------
__global__ void __launch_bounds__(256, 3) k_edge2(
    const __nv_bfloat16* __restrict__ h1in,
    const int*   __restrict__ ei,
    const float* __restrict__ W2,
    const float* __restrict__ b2)
{
    extern __shared__ char smem[];
    __nv_bfloat16* A_s = (__nv_bfloat16*)(smem + E_A);
    __nv_bfloat16* Bhi = (__nv_bfloat16*)(smem + E_BHI);
    __nv_bfloat16* Blo = (__nv_bfloat16*)(smem + E_BLO);

    const int tid = threadIdx.x;
    convert_B(W2, Bhi, Blo, tid);

    const int w = tid >> 5, l = tid & 31;
    const int g = l >> 2, tg = l & 3;
    const int mrow = (w >> 1) * 32, ncol = (w & 1) * 32;

    const uint4* src = reinterpret_cast<const uint4*>(h1in);

    for (int t = blockIdx.x; t < NTILES; t += E2_GRID) {
        const int base = t * TR;
        __syncthreads();
#pragma unroll
        for (int it = 0; it < 4; ++it) {
            int chunk = tid + it * 256;
            int row = chunk >> 3, c8 = chunk & 7;
            uint4 raw = __ldg(src + (long long)(base + row) * 8 + c8);
            const uint32_t* rw = reinterpret_cast<const uint32_t*>(&raw);
            uint32_t outp[4];
#pragma unroll
            for (int p = 0; p < 4; ++p) {
                float2 hv = __bfloat1622float2(*reinterpret_cast<const __nv_bfloat162*>(&rw[p]));
                int c = c8 * 8 + p * 2;
                float2 cs = *reinterpret_cast<const float2*>(g_coef + c);
                float2 ch = *reinterpret_cast<const float2*>(g_coef + 64 + c);
                float vx = fmaxf(fmaf(hv.x, cs.x, ch.x), 0.f);
                float vy = fmaxf(fmaf(hv.y, cs.y, ch.y), 0.f);
                __nv_bfloat162 o2 = __float22bfloat162_rn(make_float2(vx, vy));
                outp[p] = *reinterpret_cast<uint32_t*>(&o2);
            }
            *reinterpret_cast<uint4*>(A_s + row * SAB + c8 * 8) =
                make_uint4(outp[0], outp[1], outp[2], outp[3]);
        }
        __syncthreads();

        float d[2][4][4];
#pragma unroll
        for (int mt = 0; mt < 2; ++mt)
#pragma unroll
            for (int nt = 0; nt < 4; ++nt)
#pragma unroll
                for (int j = 0; j < 4; ++j) d[mt][nt][j] = 0.f;

#pragma unroll
        for (int kit = 0; kit < 4; ++kit) {
            const int kb = kit * 16 + 2 * tg;
            uint32_t a[2][4], bhi[4][2], blo[4][2];
#pragma unroll
            for (int mt = 0; mt < 2; ++mt) {
                const int r = mrow + mt * 16 + g;
                a[mt][0] = ld32bf(A_s + r * SAB + kb);
                a[mt][1] = ld32bf(A_s + (r + 8) * SAB + kb);
                a[mt][2] = ld32bf(A_s + r * SAB + kb + 8);
                a[mt][3] = ld32bf(A_s + (r + 8) * SAB + kb + 8);
            }
#pragma unroll
            for (int nt = 0; nt < 4; ++nt) {
                const int n = ncol + nt * 8 + g;
                bhi[nt][0] = ld32bf(Bhi + n * SAB + kb);
                bhi[nt][1] = ld32bf(Bhi + n * SAB + kb + 8);
                blo[nt][0] = ld32bf(Blo + n * SAB + kb);
                blo[nt][1] = ld32bf(Blo + n * SAB + kb + 8);
            }
#pragma unroll
            for (int mt = 0; mt < 2; ++mt)
#pragma unroll
                for (int nt = 0; nt < 4; ++nt) {
                    MMA16816(d[mt][nt], a[mt], bhi[nt]);
                    MMA16816(d[mt][nt], a[mt], blo[nt]);
                }
        }

#pragma unroll
        for (int mt = 0; mt < 2; ++mt) {
#pragma unroll
            for (int h = 0; h < 2; ++h) {
                const int rl = mrow + mt * 16 + g + h * 8;
                const long long rr = base + rl;
                const int rec = __ldg(ei + NE + rr);
                float* dst = g_agg + (long long)rec * 64;
#pragma unroll
                for (int nt = 0; nt < 4; ++nt) {
                    const int c = ncol + nt * 8 + 2 * tg;
                    float2 bb = __ldg(reinterpret_cast<const float2*>(b2 + c));
                    red_add2(dst + c, d[mt][nt][h * 2 + 0] + bb.x,
                                      d[mt][nt][h * 2 + 1] + bb.y);
                }
            }
        }
    }
}

// ---------------- fp32x2 node-side kernels ----------------
__device__ __forceinline__ void load_W(const float* __restrict__ W, float* W_s, int tid) {
    const float4* wg = reinterpret_cast<const float4*>(W);
    float4* ws = reinterpret_cast<float4*>(W_s);
#pragma unroll
    for (int j = 0; j < 4; ++j) ws[tid + j * NT] = wg[tid + j * NT];
}
__device__ __forceinline__ float2 unpack2(unsigned long long v) {
    float2 r;
    asm("mov.b64 {%0,%1}, %2;" : "=f"(r.x), "=f"(r.y) : "l"(v));
    return r;
}
__device__ __forceinline__ void mm64x2(const float* __restrict__ A_s,
                                       const float* __restrict__ W_s,
                                       int rg, int c4, unsigned long long acc[4][4]) {
#pragma unroll 8
    for (int k = 0; k < 64; ++k) {
        const float4 b = *reinterpret_cast<const float4*>(W_s + k * 64 + c4 * 4);
        unsigned long long bd0, bd1, bd2, bd3;
        asm("mov.b64 %0,{%1,%1};" : "=l"(bd0) : "f"(b.x));
        asm("mov.b64 %0,{%1,%1};" : "=l"(bd1) : "f"(b.y));
        asm("mov.b64 %0,{%1,%1};" : "=l"(bd2) : "f"(b.z));
        asm("mov.b64 %0,{%1,%1};" : "=l"(bd3) : "f"(b.w));
        const unsigned long long* ap =
            reinterpret_cast<const unsigned long long*>(A_s + k * SA2 + rg * 8);
#pragma unroll
        for (int i = 0; i < 4; ++i) {
            unsigned long long a = ap[i];
            asm("fma.rn.f32x2 %0, %1, %2, %0;" : "+l"(acc[i][0]) : "l"(a), "l"(bd0));
            asm("fma.rn.f32x2 %0, %1, %2, %0;" : "+l"(acc[i][1]) : "l"(a), "l"(bd1));
            asm("fma.rn.f32x2 %0, %1, %2, %0;" : "+l"(acc[i][2]) : "l"(a), "l"(bd2));
            asm("fma.rn.f32x2 %0, %1, %2, %0;" : "+l"(acc[i][3]) : "l"(a), "l"(bd3));
        }
    }
}
#define ZERO_ACC2(acc) do { \
    _Pragma("unroll") for (int _i = 0; _i < 4; ++_i) { \
        acc[_i][0]=0ull; acc[_i][1]=0ull; acc[_i][2]=0ull; acc[_i][3]=0ull; } } while (0)

__device__ __forceinline__ void stat_reduce(float* buf, int tid, int rg, int c4,
                                            const float s[4], const float q[4], int off) {
    __syncthreads();
#pragma unroll
    for (int j = 0; j < 4; ++j) {
        buf[rg * 64 + c4 * 4 + j]        = s[j];
        buf[1024 + rg * 64 + c4 * 4 + j] = q[j];
    }
    __syncthreads();
    if (tid < 128) {
        int c = tid & 63, which = tid >> 6;
        float a = 0.f;
#pragma unroll
        for (int gg = 0; gg < 16; ++gg) a += buf[which * 1024 + gg * 64 + c];
        atomicAdd(&g_stats[off + which * 64 + c], a);
    }
}

__global__ void k_zero() {
    int i = blockIdx.x * blockDim.x + threadIdx.x;
    if (i < NN * 64) g_agg[i] = 0.f;
    if (i < NN)      g_cnt[i] = 0;
    if (i < 256)     g_stats[i] = 0.f;
}
__global__ void k_inv() {
    int i = blockIdx.x * blockDim.x + threadIdx.x;
    if (i < NN) g_inv[i] = 1.0f / fmaxf((float)g_cnt[i], 1.0f);
}
__global__ void k_coef(int off, float invR,
                       const float* __restrict__ gamma, const float* __restrict__ beta) {
    int c = threadIdx.x;
    float mean = g_stats[off + c] * invR;
    float ms   = g_stats[off + 64 + c] * invR;
    float var  = ms - mean * mean;
    float sc   = gamma[c] * rsqrtf(var + EPSB);
    g_coef[off + c]      = sc;
    g_coef[off + 64 + c] = beta[c] - mean * sc;
}

// fused: xw1m = x@W1m + b1m ; xw1n = x@W1n + b1n  (x tile loaded once)
__global__ void k_gemm_bias2(const float* __restrict__ A,
                             const float* __restrict__ W1, const float* __restrict__ b1v,
                             const float* __restrict__ W2v, const float* __restrict__ b2v,
                             float* __restrict__ out1, float* __restrict__ out2) {
    extern __shared__ float smemf[];
    float* A_s = smemf;
    float* W_s = smemf + 64 * SA2;
    const int tid = threadIdx.x;
    const int base = blockIdx.x * TR;
    load_W(W1, W_s, tid);
    load_W(W2v, W_s + 4096, tid);
#pragma unroll
    for (int j = 0; j < 32; ++j) {
        int idx = tid + j * NT;
        int k = idx & 63, row = idx >> 6;
        int r = base + row; if (r > NN - 1) r = NN - 1;
        A_s[k * SA2 + row] = A[r * 64 + k];
    }
    __syncthreads();
    const int c4 = tid & 15, rg = tid >> 4;
    unsigned long long acc[4][4];
#pragma unroll
    for (int which = 0; which < 2; ++which) {
        ZERO_ACC2(acc);
        mm64x2(A_s, W_s + which * 4096, rg, c4, acc);
        const float* bias = (which == 0) ? b1v : b2v;
        float* out = (which == 0) ? out1 : out2;
        const float4 bb = *reinterpret_cast<const float4*>(bias + c4 * 4);
#pragma unroll
        for (int i = 0; i < 4; ++i) {
            float2 p0 = unpack2(acc[i][0]), p1 = unpack2(acc[i][1]);
            float2 p2 = unpack2(acc[i][2]), p3 = unpack2(acc[i][3]);
            int r0 = base + rg * 8 + 2 * i;
            if (r0 < NN)
                *reinterpret_cast<float4*>(out + r0 * 64 + c4 * 4) =
                    make_float4(p0.x + bb.x, p1.x + bb.y, p2.x + bb.z, p3.x + bb.w);
            if (r0 + 1 < NN)
                *reinterpret_cast<float4*>(out + (r0 + 1) * 64 + c4 * 4) =
                    make_float4(p0.y + bb.x, p1.y + bb.y, p2.y + bb.z, p3.y + bb.w);
        }
    }
}

__global__ void k_node1(const float* __restrict__ Wbot) {
    extern __shared__ float smemf[];
    float* A_s = smemf;
    float* W_s = smemf + 64 * SA2;
    const int tid = threadIdx.x;
    const int base = blockIdx.x * TR;
    load_W(Wbot, W_s, tid);
#pragma unroll
    for (int j = 0; j < 32; ++j) {
        int idx = tid + j * NT;
        int k = idx & 63, row = idx >> 6;
        int r = base + row; if (r > NN - 1) r = NN - 1;
        A_s[k * SA2 + row] = g_agg[r * 64 + k] * g_inv[r];
    }
    __syncthreads();
    const int c4 = tid & 15, rg = tid >> 4;
    unsigned long long acc[4][4];
    ZERO_ACC2(acc);
    mm64x2(A_s, W_s, rg, c4, acc);
    float s[4] = {0.f,0.f,0.f,0.f}, q[4] = {0.f,0.f,0.f,0.f};
#pragma unroll
    for (int i = 0; i < 4; ++i) {
        float2 p0 = unpack2(acc[i][0]), p1 = unpack2(acc[i][1]);
        float2 p2 = unpack2(acc[i][2]), p3 = unpack2(acc[i][3]);
        int r0 = base + rg * 8 + 2 * i;
        if (r0 < NN) {
            float4 xw = *reinterpret_cast<const float4*>(g_xw1n + r0 * 64 + c4 * 4);
            float4 v = make_float4(p0.x + xw.x, p1.x + xw.y, p2.x + xw.z, p3.x + xw.w);
            *reinterpret_cast<float4*>(g_hn + r0 * 64 + c4 * 4) = v;
            s[0] += v.x; q[0] += v.x * v.x; s[1] += v.y; q[1] += v.y * v.y;
            s[2] += v.z; q[2] += v.z * v.z; s[3] += v.w; q[3] += v.w * v.w;
        }
        if (r0 + 1 < NN) {
            float4 xw = *reinterpret_cast<const float4*>(g_xw1n + (r0 + 1) * 64 + c4 * 4);
            float4 v = make_float4(p0.y + xw.x, p1.y + xw.y, p2.y + xw.z, p3.y + xw.w);
            *reinterpret_cast<float4*>(g_hn + (r0 + 1) * 64 + c4 * 4) = v;
            s[0] += v.x; q[0] += v.x * v.x; s[1] += v.y; q[1] += v.y * v.y;
            s[2] += v.z; q[2] += v.z * v.z; s[3] += v.w; q[3] += v.w * v.w;
        }
    }
    stat_reduce(A_s, tid, rg, c4, s, q, 128);
}
__global__ void k_node2(const float* __restrict__ W2,
                        const float* __restrict__ b2,
                        float* __restrict__ out) {
    extern __shared__ float smemf[];
    float* A_s = smemf;
    float* W_s = smemf + 64 * SA2;
    const int tid = threadIdx.x;
    const int base = blockIdx.x * TR;
    load_W(W2, W_s, tid);
    const float cs = g_coef[128 + (tid & 63)];
    const float ch = g_coef[192 + (tid & 63)];
#pragma unroll
    for (int j = 0; j < 32; ++j) {
        int idx = tid + j * NT;
        int k = idx & 63, row = idx >> 6;
        int r = base + row; if (r > NN - 1) r = NN - 1;
        float v = fmaf(g_hn[r * 64 + k], cs, ch);
        A_s[k * SA2 + row] = fmaxf(v, 0.f);
    }
    __syncthreads();
    const int c4 = tid & 15, rg = tid >> 4;
    unsigned long long acc[4][4];
    ZERO_ACC2(acc);
    mm64x2(A_s, W_s, rg, c4, acc);
    const float4 bb = *reinterpret_cast<const float4*>(b2 + c4 * 4);
#pragma unroll
    for (int i = 0; i < 4; ++i) {
        float2 p0 = unpack2(acc[i][0]), p1 = unpack2(acc[i][1]);
        float2 p2 = unpack2(acc[i][2]), p3 = unpack2(acc[i][3]);
        int r0 = base + rg * 8 + 2 * i;
        if (r0 < NN)
            *reinterpret_cast<float4*>(out + r0 * 64 + c4 * 4) =
                make_float4(p0.x + bb.x, p1.x + bb.y, p2.x + bb.z, p3.x + bb.w);
        if (r0 + 1 < NN)
            *reinterpret_cast<float4*>(out + (r0 + 1) * 64 + c4 * 4) =
                make_float4(p0.y + bb.x, p1.y + bb.y, p2.y + bb.z, p3.y + bb.w);
    }
}

// ---------------- launch ----------------
extern "C" void kernel_launch(void* const* d_in, const int* in_sizes, int n_in,
                              void* d_out, int out_size) {
    const float* x   = (const float*)d_in[0];
    const int*   ei  = (const int*)d_in[1];
    const float* ea  = (const float*)d_in[2];
    const float* w1m = (const float*)d_in[5];
    const float* b1m = (const float*)d_in[6];
    const float* gm  = (const float*)d_in[7];
    const float* bm  = (const float*)d_in[8];
    const float* w2m = (const float*)d_in[9];
    const float* b2m = (const float*)d_in[10];
    const float* w1n = (const float*)d_in[11];
    const float* b1n = (const float*)d_in[12];
    const float* gn  = (const float*)d_in[13];
    const float* bn  = (const float*)d_in[14];
    const float* w2n = (const float*)d_in[15];
    const float* b2n = (const float*)d_in[16];
    float* out = (float*)d_out;

    cudaFuncSetAttribute(k_gemm_bias2, cudaFuncAttributeMaxDynamicSharedMemorySize, GB2_BYTES);
    cudaFuncSetAttribute(k_node1,      cudaFuncAttributeMaxDynamicSharedMemorySize, SMEM_BYTES);
    cudaFuncSetAttribute(k_node2,      cudaFuncAttributeMaxDynamicSharedMemorySize, SMEM_BYTES);
    cudaFuncSetAttribute(k_edge1,      cudaFuncAttributeMaxDynamicSharedMemorySize, E_SMEM);
    cudaFuncSetAttribute(k_edge2,      cudaFuncAttributeMaxDynamicSharedMemorySize, E_SMEM);

    float *p_xw1m, *p_xw1n;
    __nv_bfloat16* p_h1;
    cudaGetSymbolAddress((void**)&p_xw1m, g_xw1m);
    cudaGetSymbolAddress((void**)&p_xw1n, g_xw1n);
    cudaGetSymbolAddress((void**)&p_h1,   g_h1);

    const int nodeBlocks = (NN + TR - 1) / TR;

    k_zero<<<(NN * 64 + NT - 1) / NT, NT>>>();
    k_gemm_bias2<<<nodeBlocks, NT, GB2_BYTES>>>(x, w1m, b1m, w1n, b1n, p_xw1m, p_xw1n);
    k_edge1<<<E1_GRID, 256, E_SMEM>>>(ea, p_h1, ei, w1m + 64 * 64);
    k_inv<<<(NN + NT - 1) / NT, NT>>>();
    k_coef<<<1, 64>>>(0, 1.0f / (float)NE, gm, bm);
    k_edge2<<<E2_GRID, 256, E_SMEM>>>(p_h1, ei, w2m, b2m);
    k_node1<<<nodeBlocks, NT, SMEM_BYTES>>>(w1n + 64 * 64);
    k_coef<<<1, 64>>>(128, 1.0f / (float)NN, gn, bn);
    k_node2<<<nodeBlocks, NT, SMEM_BYTES>>>(w2n, b2n, out);
}